// round 1
// baseline (speedup 1.0000x reference)
#include <cuda_runtime.h>

// Problem constants (fixed shapes from reference)
namespace {
constexpr int NROWS = 65536;   // total neighbors
constexpr int BSAMP = 4096;    // samples
constexpr int INSZ  = 64;      // neighbor_t feature dim
constexpr int HID   = 512;     // hidden
constexpr int DDIM  = 256;     // dist dim
constexpr int EMBK  = INSZ + HID + DDIM;  // 832
constexpr int G3    = 3 * HID;            // 1536

constexpr int BM = 128, BN = 64, BK = 16, NTHR = 256;
}

// Scratch (no allocation allowed -> __device__ globals)
__device__ float g_emb[(size_t)NROWS * HID];   // 128 MB
__device__ float g_gi [(size_t)NROWS * G3];    // 384 MB
__device__ float g_gh [(size_t)NROWS * G3];    // 384 MB

// AMODE 0: A is the gathered/concatenated X (neighbor_t | traj[sid] | dist)
// AMODE 1: A is a plain row-major [M,K] matrix (lda == K)
// TRANSB  : B given as row-major [Ncols, K] (PyTorch weight), effective B[k,j] = W[j*ldb+k]
template<int AMODE, bool TRANSB, bool RELU>
__global__ void __launch_bounds__(NTHR)
gemm_k(const float* __restrict__ A,
       const float* __restrict__ neigh,
       const float* __restrict__ traj,
       const float* __restrict__ dist,
       const int*   __restrict__ starts,
       const float* __restrict__ Bmat,
       const float* __restrict__ bias,
       float* __restrict__ C,
       int K, int ldb, int ldc)
{
    __shared__ float As[BK][BM];
    __shared__ float Bs[BK][BN];
    __shared__ int   sids[BM];

    const int tid = threadIdx.x;
    const int m0 = blockIdx.x * BM;
    const int n0 = blockIdx.y * BN;

    if (AMODE == 0) {
        if (tid < BM) {
            int row = m0 + tid;
            // upper_bound(starts, row) - 1
            int lo = 0, hi = BSAMP;
            while (lo < hi) {
                int mid = (lo + hi) >> 1;
                if (starts[mid] <= row) lo = mid + 1; else hi = mid;
            }
            sids[tid] = lo - 1;
        }
        __syncthreads();
    }

    const int tx = tid & 15;     // 16 col-groups of 4
    const int ty = tid >> 4;     // 16 row-groups of 8

    float acc[8][4];
    #pragma unroll
    for (int i = 0; i < 8; i++)
        #pragma unroll
        for (int j = 0; j < 4; j++) acc[i][j] = 0.f;

    const int ac4 = tid & 3;     // A: float4 column within BK
    const int ar  = tid >> 2;    // A: row 0..63 (two passes)
    const int bkr = tid >> 4;    // B (!TRANSB): k row 0..15
    const int bc4 = tid & 15;    // B (!TRANSB): col float4
    const int tj  = tid >> 2;    // B (TRANSB): output-col 0..63
    const int tkq = tid & 3;     // B (TRANSB): k float4

    for (int k0 = 0; k0 < K; k0 += BK) {
        // ---- A tile: [BM, BK] -> As[k][m] ----
        #pragma unroll
        for (int rr = 0; rr < 2; rr++) {
            int row = ar + rr * 64;
            int gm  = m0 + row;
            float4 v;
            if (AMODE == 1) {
                v = *(const float4*)(A + (size_t)gm * K + (k0 + ac4 * 4));
            } else {
                // sections: [0,64) neigh | [64,576) traj[sid] | [576,832) dist
                if (k0 < INSZ)
                    v = *(const float4*)(neigh + (size_t)gm * INSZ + (k0 + ac4 * 4));
                else if (k0 < INSZ + HID)
                    v = *(const float4*)(traj + (size_t)sids[row] * HID + (k0 - INSZ + ac4 * 4));
                else
                    v = *(const float4*)(dist + (size_t)gm * DDIM + (k0 - INSZ - HID + ac4 * 4));
            }
            As[ac4*4+0][row] = v.x;
            As[ac4*4+1][row] = v.y;
            As[ac4*4+2][row] = v.z;
            As[ac4*4+3][row] = v.w;
        }
        // ---- B tile: [BK, BN] -> Bs[k][n] ----
        if (!TRANSB) {
            float4 v = *(const float4*)(Bmat + (size_t)(k0 + bkr) * ldb + (n0 + bc4 * 4));
            *(float4*)&Bs[bkr][bc4 * 4] = v;
        } else {
            float4 v = *(const float4*)(Bmat + (size_t)(n0 + tj) * ldb + (k0 + tkq * 4));
            Bs[tkq*4+0][tj] = v.x;
            Bs[tkq*4+1][tj] = v.y;
            Bs[tkq*4+2][tj] = v.z;
            Bs[tkq*4+3][tj] = v.w;
        }
        __syncthreads();

        #pragma unroll
        for (int k = 0; k < BK; k++) {
            float a[8], b[4];
            *(float4*)&a[0] = *(const float4*)&As[k][ty * 8];
            *(float4*)&a[4] = *(const float4*)&As[k][ty * 8 + 4];
            *(float4*)&b[0] = *(const float4*)&Bs[k][tx * 4];
            #pragma unroll
            for (int i = 0; i < 8; i++)
                #pragma unroll
                for (int j = 0; j < 4; j++)
                    acc[i][j] = fmaf(a[i], b[j], acc[i][j]);
        }
        __syncthreads();
    }

    float4 bv = *(const float4*)(bias + n0 + tx * 4);
    #pragma unroll
    for (int i = 0; i < 8; i++) {
        int row = m0 + ty * 8 + i;
        float4 o;
        o.x = acc[i][0] + bv.x;
        o.y = acc[i][1] + bv.y;
        o.z = acc[i][2] + bv.z;
        o.w = acc[i][3] + bv.w;
        if (RELU) {
            o.x = fmaxf(o.x, 0.f);
            o.y = fmaxf(o.y, 0.f);
            o.z = fmaxf(o.z, 0.f);
            o.w = fmaxf(o.w, 0.f);
        }
        *(float4*)(C + (size_t)row * ldc + (n0 + tx * 4)) = o;
    }
}

__device__ __forceinline__ float gru1(float ir, float iz, float inn,
                                      float hr, float hz, float hn, float h)
{
    float r = 1.f / (1.f + expf(-(ir + hr)));
    float z = 1.f / (1.f + expf(-(iz + hz)));
    float nn = tanhf(fmaf(r, hn, inn));
    return fmaf(z, h - nn, nn);   // (1-z)*n + z*h
}

__global__ void __launch_bounds__(256)
gates_k(const float* __restrict__ gi, const float* __restrict__ gh,
        const float* __restrict__ ht, float* __restrict__ out)
{
    int idx = blockIdx.x * 256 + threadIdx.x;   // one float4 of output
    int n  = idx >> 7;             // HID/4 = 128 float4 per row
    int h4 = (idx & 127) << 2;
    const float* gir = gi + (size_t)n * G3;
    const float* ghr = gh + (size_t)n * G3;
    float4 ir = *(const float4*)(gir + h4);
    float4 iz = *(const float4*)(gir + HID + h4);
    float4 in_= *(const float4*)(gir + 2*HID + h4);
    float4 hr = *(const float4*)(ghr + h4);
    float4 hz = *(const float4*)(ghr + HID + h4);
    float4 hn = *(const float4*)(ghr + 2*HID + h4);
    float4 h  = *(const float4*)(ht + (size_t)n * HID + h4);
    float4 o;
    o.x = gru1(ir.x, iz.x, in_.x, hr.x, hz.x, hn.x, h.x);
    o.y = gru1(ir.y, iz.y, in_.y, hr.y, hz.y, hn.y, h.y);
    o.z = gru1(ir.z, iz.z, in_.z, hr.z, hz.z, hn.z, h.z);
    o.w = gru1(ir.w, iz.w, in_.w, hr.w, hz.w, hn.w, h.w);
    *(float4*)(out + (size_t)n * HID + h4) = o;
}

extern "C" void kernel_launch(void* const* d_in, const int* in_sizes, int n_in,
                              void* d_out, int out_size)
{
    const float* traj  = (const float*)d_in[0];
    const float* neigh = (const float*)d_in[1];
    const float* dist  = (const float*)d_in[2];
    const float* ht    = (const float*)d_in[3];
    const float* W_emb = (const float*)d_in[4];
    const float* b_emb = (const float*)d_in[5];
    const float* w_ih  = (const float*)d_in[6];
    const float* w_hh  = (const float*)d_in[7];
    const float* b_ih  = (const float*)d_in[8];
    const float* b_hh  = (const float*)d_in[9];
    const int*   starts= (const int*)  d_in[10];
    float* out = (float*)d_out;

    float *emb_p, *gi_p, *gh_p;
    cudaGetSymbolAddress((void**)&emb_p, g_emb);
    cudaGetSymbolAddress((void**)&gi_p,  g_gi);
    cudaGetSymbolAddress((void**)&gh_p,  g_gh);

    // emb = relu(X @ W_emb + b_emb)   X gathered on the fly
    dim3 g1(NROWS / BM, HID / BN);
    gemm_k<0, false, true><<<g1, NTHR>>>(nullptr, neigh, traj, dist, starts,
                                         W_emb, b_emb, emb_p, EMBK, HID, HID);
    // gi = emb @ w_ih.T + b_ih ;  gh = ht @ w_hh.T + b_hh
    dim3 g2(NROWS / BM, G3 / BN);
    gemm_k<1, true, false><<<g2, NTHR>>>(emb_p, nullptr, nullptr, nullptr, nullptr,
                                         w_ih, b_ih, gi_p, HID, HID, G3);
    gemm_k<1, true, false><<<g2, NTHR>>>(ht, nullptr, nullptr, nullptr, nullptr,
                                         w_hh, b_hh, gh_p, HID, HID, G3);
    // GRU gates
    int total4 = NROWS * HID / 4;
    gates_k<<<total4 / 256, 256>>>(gi_p, gh_p, ht, out);
}

// round 5
// speedup vs baseline: 3.0353x; 3.0353x over previous
#include <cuda_runtime.h>
#include <cstdint>

// ---------------- problem constants ----------------
namespace {
constexpr int NROWS = 65536;
constexpr int BSAMP = 4096;
constexpr int INSZ  = 64;
constexpr int HID   = 512;
constexpr int DDIM  = 256;
constexpr int EMBK  = INSZ + HID + DDIM;  // 832
constexpr int G3    = 3 * HID;            // 1536

constexpr int BM = 128, BN = 128, BK = 16, NTHR = 256;
constexpr int LDS_ = 20;                              // padded smem row stride (floats)
constexpr int STAGE_FLOATS = BM * LDS_ + BN * LDS_;   // 5120 floats / stage
constexpr int NSTAGE = 3;
constexpr int SMEM_BYTES = NSTAGE * STAGE_FLOATS * 4 + 512;  // + sids
}

// ---------------- scratch (__device__ globals) ----------------
__device__ float g_emb [(size_t)NROWS * HID];
__device__ float g_gi  [(size_t)NROWS * G3];
__device__ float g_gh  [(size_t)NROWS * G3];
__device__ float g_wt  [(size_t)HID * EMBK];    // W_emb^T, tf32-rounded
__device__ float g_wih [(size_t)G3 * HID];      // tf32-rounded
__device__ float g_whh [(size_t)G3 * HID];
__device__ float g_nt  [(size_t)NROWS * INSZ];  // tf32 copies of A-side inputs
__device__ float g_ds  [(size_t)NROWS * DDIM];
__device__ float g_tj  [(size_t)BSAMP * HID];
__device__ float g_htt [(size_t)NROWS * HID];

// ---------------- helpers ----------------
__device__ __forceinline__ float tf32r(float x) {
    uint32_t u;
    asm("cvt.rna.tf32.f32 %0, %1;" : "=r"(u) : "f"(x));
    return __uint_as_float(u);
}
__device__ __forceinline__ uint32_t smem_u32(const void* p) {
    uint32_t a;
    asm("{ .reg .u64 t; cvta.to.shared.u64 t, %1; cvt.u32.u64 %0, t; }" : "=r"(a) : "l"(p));
    return a;
}
#define CP_ASYNC16(dst, src) \
    asm volatile("cp.async.cg.shared.global [%0], [%1], 16;\n" :: "r"(dst), "l"(src))

__device__ __forceinline__ void mma_tf32(float* c, const uint32_t* a, const uint32_t* b) {
    asm volatile(
        "mma.sync.aligned.m16n8k8.row.col.f32.tf32.tf32.f32 "
        "{%0,%1,%2,%3}, {%4,%5,%6,%7}, {%8,%9}, {%0,%1,%2,%3};"
        : "+f"(c[0]), "+f"(c[1]), "+f"(c[2]), "+f"(c[3])
        : "r"(a[0]), "r"(a[1]), "r"(a[2]), "r"(a[3]), "r"(b[0]), "r"(b[1]));
}

// ---------------- prep kernels ----------------
__global__ void cvt_k(const float* __restrict__ in, float* __restrict__ out, int n4) {
    int i = blockIdx.x * blockDim.x + threadIdx.x;
    if (i < n4) {
        float4 v = ((const float4*)in)[i];
        v.x = tf32r(v.x); v.y = tf32r(v.y); v.z = tf32r(v.z); v.w = tf32r(v.w);
        ((float4*)out)[i] = v;
    }
}

__global__ void transpose_cvt_k(const float* __restrict__ W, float* __restrict__ Wt) {
    __shared__ float t[32][33];
    int bx = blockIdx.x * 32;   // k (EMBK)
    int by = blockIdx.y * 32;   // n (HID)
    int tx = threadIdx.x, ty = threadIdx.y;
    #pragma unroll
    for (int i = 0; i < 4; i++)
        t[ty + i * 8][tx] = W[(size_t)(bx + ty + i * 8) * HID + (by + tx)];
    __syncthreads();
    #pragma unroll
    for (int i = 0; i < 4; i++)
        Wt[(size_t)(by + ty + i * 8) * EMBK + (bx + tx)] = tf32r(t[tx][ty + i * 8]);
}

// ---------------- tf32 mma.sync GEMM ----------------
// C[m, n0:n0+BN] = act( A[m,:K] @ B[n,:K]^T + bias )
// AMODE 0: A gathered (neigh | traj[sid] | dist), AMODE 1: plain row-major.
template<int AMODE, bool RELU, bool CVTOUT>
__global__ void __launch_bounds__(NTHR, 2)
gemm_tc(const float* __restrict__ A,
        const float* __restrict__ neigh,
        const float* __restrict__ traj,
        const float* __restrict__ dist,
        const int*   __restrict__ starts,
        const float* __restrict__ B,
        const float* __restrict__ bias,
        float* __restrict__ C,
        int K, int ldb, int ldc)
{
    extern __shared__ float sm[];
    int* sids = (int*)(sm + NSTAGE * STAGE_FLOATS);

    const int tid  = threadIdx.x;
    const int lane = tid & 31;
    const int warp = tid >> 5;
    const int wm = warp >> 2;        // 0..1 : 64-row slab
    const int wn = warp & 3;         // 0..3 : 32-col slab
    const int m0 = blockIdx.x * BM;
    const int n0 = blockIdx.y * BN;

    if (AMODE == 0 && tid < BM) {
        int row = m0 + tid;
        int lo = 0, hi = BSAMP;
        while (lo < hi) {
            int mid = (lo + hi) >> 1;
            if (starts[mid] <= row) lo = mid + 1; else hi = mid;
        }
        sids[tid] = lo - 1;
    }
    if (AMODE == 0) __syncthreads();

    const uint32_t sbase = smem_u32(sm);

    auto load_stage = [&](int s) {
        const uint32_t st = sbase + (uint32_t)((s % NSTAGE) * STAGE_FLOATS) * 4u;
        const int k0 = s * BK;
        // A tile: 128 rows x 16 floats = 512 float4
        #pragma unroll
        for (int i = 0; i < 2; i++) {
            int q = tid + i * NTHR;
            int row = q >> 2, c4 = q & 3;
            uint32_t dst = st + (uint32_t)(row * LDS_ + c4 * 4) * 4u;
            const float* src;
            int gm = m0 + row;
            if (AMODE == 1) {
                src = A + (size_t)gm * K + (k0 + c4 * 4);
            } else {
                if (k0 < INSZ)
                    src = neigh + (size_t)gm * INSZ + (k0 + c4 * 4);
                else if (k0 < INSZ + HID)
                    src = traj + (size_t)sids[row] * HID + (k0 - INSZ + c4 * 4);
                else
                    src = dist + (size_t)gm * DDIM + (k0 - INSZ - HID + c4 * 4);
            }
            CP_ASYNC16(dst, src);
        }
        // B tile: 128 rows x 16 floats
        const uint32_t bb = st + (uint32_t)(BM * LDS_) * 4u;
        #pragma unroll
        for (int i = 0; i < 2; i++) {
            int q = tid + i * NTHR;
            int row = q >> 2, c4 = q & 3;
            uint32_t dst = bb + (uint32_t)(row * LDS_ + c4 * 4) * 4u;
            const float* src = B + (size_t)(n0 + row) * ldb + (k0 + c4 * 4);
            CP_ASYNC16(dst, src);
        }
    };

    float acc[4][4][4];
    #pragma unroll
    for (int mt = 0; mt < 4; mt++)
        #pragma unroll
        for (int nt = 0; nt < 4; nt++)
            #pragma unroll
            for (int j = 0; j < 4; j++) acc[mt][nt][j] = 0.f;

    const int NS = K / BK;
    load_stage(0);
    asm volatile("cp.async.commit_group;\n" ::: "memory");
    load_stage(1);
    asm volatile("cp.async.commit_group;\n" ::: "memory");

    for (int s = 0; s < NS; ++s) {
        if (s + 2 < NS) load_stage(s + 2);
        asm volatile("cp.async.commit_group;\n" ::: "memory");
        asm volatile("cp.async.wait_group 2;\n" ::: "memory");
        __syncthreads();

        const float* As = sm + (s % NSTAGE) * STAGE_FLOATS;
        const float* Bs = As + BM * LDS_;
        #pragma unroll
        for (int kk = 0; kk < 2; kk++) {
            uint32_t a[4][4], b[4][2];
            #pragma unroll
            for (int mt = 0; mt < 4; mt++) {
                const float* p = As + (wm * 64 + mt * 16 + (lane >> 2)) * LDS_ + kk * 8 + (lane & 3);
                a[mt][0] = __float_as_uint(p[0]);
                a[mt][1] = __float_as_uint(p[8 * LDS_]);
                a[mt][2] = __float_as_uint(p[4]);
                a[mt][3] = __float_as_uint(p[8 * LDS_ + 4]);
            }
            #pragma unroll
            for (int nt = 0; nt < 4; nt++) {
                const float* p = Bs + (wn * 32 + nt * 8 + (lane >> 2)) * LDS_ + kk * 8 + (lane & 3);
                b[nt][0] = __float_as_uint(p[0]);
                b[nt][1] = __float_as_uint(p[4]);
            }
            #pragma unroll
            for (int mt = 0; mt < 4; mt++)
                #pragma unroll
                for (int nt = 0; nt < 4; nt++)
                    mma_tf32(acc[mt][nt], a[mt], b[nt]);
        }
        __syncthreads();
    }

    // ---------------- epilogue ----------------
    #pragma unroll
    for (int mt = 0; mt < 4; mt++) {
        #pragma unroll
        for (int nt = 0; nt < 4; nt++) {
            int col = n0 + wn * 32 + nt * 8 + 2 * (lane & 3);
            float2 bv = *(const float2*)(bias + col);
            int r0 = m0 + wm * 64 + mt * 16 + (lane >> 2);
            float v0 = acc[mt][nt][0] + bv.x;
            float v1 = acc[mt][nt][1] + bv.y;
            float v2 = acc[mt][nt][2] + bv.x;
            float v3 = acc[mt][nt][3] + bv.y;
            if (RELU) {
                v0 = fmaxf(v0, 0.f); v1 = fmaxf(v1, 0.f);
                v2 = fmaxf(v2, 0.f); v3 = fmaxf(v3, 0.f);
            }
            if (CVTOUT) {
                v0 = tf32r(v0); v1 = tf32r(v1); v2 = tf32r(v2); v3 = tf32r(v3);
            }
            float2 o0 = make_float2(v0, v1);
            float2 o1 = make_float2(v2, v3);
            *(float2*)(C + (size_t)r0 * ldc + col) = o0;
            *(float2*)(C + (size_t)(r0 + 8) * ldc + col) = o1;
        }
    }
}

// ---------------- GRU gates (HBM-bound already) ----------------
__device__ __forceinline__ float gru1(float ir, float iz, float inn,
                                      float hr, float hz, float hn, float h)
{
    float r = 1.f / (1.f + expf(-(ir + hr)));
    float z = 1.f / (1.f + expf(-(iz + hz)));
    float nn = tanhf(fmaf(r, hn, inn));
    return fmaf(z, h - nn, nn);
}

__global__ void __launch_bounds__(256)
gates_k(const float* __restrict__ gi, const float* __restrict__ gh,
        const float* __restrict__ ht, float* __restrict__ out)
{
    int idx = blockIdx.x * 256 + threadIdx.x;
    int n  = idx >> 7;
    int h4 = (idx & 127) << 2;
    const float* gir = gi + (size_t)n * G3;
    const float* ghr = gh + (size_t)n * G3;
    float4 ir = *(const float4*)(gir + h4);
    float4 iz = *(const float4*)(gir + HID + h4);
    float4 in_= *(const float4*)(gir + 2 * HID + h4);
    float4 hr = *(const float4*)(ghr + h4);
    float4 hz = *(const float4*)(ghr + HID + h4);
    float4 hn = *(const float4*)(ghr + 2 * HID + h4);
    float4 h  = *(const float4*)(ht + (size_t)n * HID + h4);
    float4 o;
    o.x = gru1(ir.x, iz.x, in_.x, hr.x, hz.x, hn.x, h.x);
    o.y = gru1(ir.y, iz.y, in_.y, hr.y, hz.y, hn.y, h.y);
    o.z = gru1(ir.z, iz.z, in_.z, hr.z, hz.z, hn.z, h.z);
    o.w = gru1(ir.w, iz.w, in_.w, hr.w, hz.w, hn.w, h.w);
    *(float4*)(out + (size_t)n * HID + h4) = o;
}

// ---------------- host ----------------
extern "C" void kernel_launch(void* const* d_in, const int* in_sizes, int n_in,
                              void* d_out, int out_size)
{
    const float* traj  = (const float*)d_in[0];
    const float* neigh = (const float*)d_in[1];
    const float* dist  = (const float*)d_in[2];
    const float* ht    = (const float*)d_in[3];
    const float* W_emb = (const float*)d_in[4];
    const float* b_emb = (const float*)d_in[5];
    const float* w_ih  = (const float*)d_in[6];
    const float* w_hh  = (const float*)d_in[7];
    const float* b_ih  = (const float*)d_in[8];
    const float* b_hh  = (const float*)d_in[9];
    const int*   starts= (const int*)  d_in[10];
    float* out = (float*)d_out;

    float *emb_p, *gi_p, *gh_p, *wt_p, *wih_p, *whh_p, *nt_p, *ds_p, *tj_p, *htt_p;
    cudaGetSymbolAddress((void**)&emb_p, g_emb);
    cudaGetSymbolAddress((void**)&gi_p,  g_gi);
    cudaGetSymbolAddress((void**)&gh_p,  g_gh);
    cudaGetSymbolAddress((void**)&wt_p,  g_wt);
    cudaGetSymbolAddress((void**)&wih_p, g_wih);
    cudaGetSymbolAddress((void**)&whh_p, g_whh);
    cudaGetSymbolAddress((void**)&nt_p,  g_nt);
    cudaGetSymbolAddress((void**)&ds_p,  g_ds);
    cudaGetSymbolAddress((void**)&tj_p,  g_tj);
    cudaGetSymbolAddress((void**)&htt_p, g_htt);

    cudaFuncSetAttribute(gemm_tc<0, true, true>,
                         cudaFuncAttributeMaxDynamicSharedMemorySize, SMEM_BYTES);
    cudaFuncSetAttribute(gemm_tc<1, false, false>,
                         cudaFuncAttributeMaxDynamicSharedMemorySize, SMEM_BYTES);

    // tf32 (round-to-nearest) pre-conversion of all GEMM operands
    auto cvt = [&](const float* in, float* o, size_t n) {
        int n4 = (int)(n / 4);
        cvt_k<<<(n4 + 255) / 256, 256>>>(in, o, n4);
    };
    cvt(neigh, nt_p,  (size_t)NROWS * INSZ);
    cvt(dist,  ds_p,  (size_t)NROWS * DDIM);
    cvt(traj,  tj_p,  (size_t)BSAMP * HID);
    cvt(ht,    htt_p, (size_t)NROWS * HID);
    cvt(w_ih,  wih_p, (size_t)G3 * HID);
    cvt(w_hh,  whh_p, (size_t)G3 * HID);
    transpose_cvt_k<<<dim3(EMBK / 32, HID / 32), dim3(32, 8)>>>(W_emb, wt_p);

    // emb = relu(X @ W_emb + b), X gathered; output tf32-rounded for GEMM2
    gemm_tc<0, true, true><<<dim3(NROWS / BM, HID / BN), NTHR, SMEM_BYTES>>>(
        nullptr, nt_p, tj_p, ds_p, starts, wt_p, b_emb, emb_p, EMBK, EMBK, HID);

    // gi = emb @ w_ih^T + b_ih
    gemm_tc<1, false, false><<<dim3(NROWS / BM, G3 / BN), NTHR, SMEM_BYTES>>>(
        emb_p, nullptr, nullptr, nullptr, nullptr, wih_p, b_ih, gi_p, HID, HID, G3);

    // gh = ht @ w_hh^T + b_hh
    gemm_tc<1, false, false><<<dim3(NROWS / BM, G3 / BN), NTHR, SMEM_BYTES>>>(
        htt_p, nullptr, nullptr, nullptr, nullptr, whh_p, b_hh, gh_p, HID, HID, G3);

    gates_k<<<(NROWS * HID / 4) / 256, 256>>>(gi_p, gh_p, ht, out);
}

// round 6
// speedup vs baseline: 5.6020x; 1.8456x over previous
#include <cuda_runtime.h>
#include <cuda_fp16.h>
#include <cstdint>

// ---------------- problem constants ----------------
namespace {
constexpr int NROWS = 65536;
constexpr int BSAMP = 4096;
constexpr int INSZ  = 64;
constexpr int HID   = 512;
constexpr int DDIM  = 256;
constexpr int EMBK  = INSZ + HID + DDIM;  // 832
constexpr int G3    = 3 * HID;            // 1536

constexpr int BM = 128, BN = 128, BK = 32, NTHR = 256;
constexpr int LDSH = 40;                         // padded smem row stride (halves) = 80B
constexpr int TILE_BYTES  = BM * LDSH * 2;       // 10240 per operand tile
constexpr int STAGE_BYTES = 2 * TILE_BYTES;      // 20480
constexpr int NSTAGE = 3;
constexpr int SMEM_BYTES = NSTAGE * STAGE_BYTES + 512;   // + sids
}

// ---------------- scratch (__device__ globals) ----------------
__device__ float  g_gi  [(size_t)NROWS * G3];
__device__ float  g_gh  [(size_t)NROWS * G3];
__device__ __half g_emb [(size_t)NROWS * HID];
__device__ __half g_wt  [(size_t)HID * EMBK];    // W_emb^T in half
__device__ __half g_wih [(size_t)G3 * HID];
__device__ __half g_whh [(size_t)G3 * HID];
__device__ __half g_nt  [(size_t)NROWS * INSZ];  // half copies of A-side inputs
__device__ __half g_ds  [(size_t)NROWS * DDIM];
__device__ __half g_tj  [(size_t)BSAMP * HID];
__device__ __half g_htt [(size_t)NROWS * HID];

// ---------------- helpers ----------------
__device__ __forceinline__ uint32_t smem_u32(const void* p) {
    uint32_t a;
    asm("{ .reg .u64 t; cvta.to.shared.u64 t, %1; cvt.u32.u64 %0, t; }" : "=r"(a) : "l"(p));
    return a;
}
#define CP_ASYNC16(dst, src) \
    asm volatile("cp.async.cg.shared.global [%0], [%1], 16;\n" :: "r"(dst), "l"(src))

__device__ __forceinline__ void mma_f16(float* c, const uint32_t* a, const uint32_t* b) {
    asm volatile(
        "mma.sync.aligned.m16n8k16.row.col.f32.f16.f16.f32 "
        "{%0,%1,%2,%3}, {%4,%5,%6,%7}, {%8,%9}, {%0,%1,%2,%3};"
        : "+f"(c[0]), "+f"(c[1]), "+f"(c[2]), "+f"(c[3])
        : "r"(a[0]), "r"(a[1]), "r"(a[2]), "r"(a[3]), "r"(b[0]), "r"(b[1]));
}
#define LDSM_X4(r, addr) \
    asm volatile("ldmatrix.sync.aligned.m8n8.x4.shared.b16 {%0,%1,%2,%3}, [%4];" \
                 : "=r"((r)[0]), "=r"((r)[1]), "=r"((r)[2]), "=r"((r)[3]) : "r"(addr))
#define LDSM_X2(r, addr) \
    asm volatile("ldmatrix.sync.aligned.m8n8.x2.shared.b16 {%0,%1}, [%2];" \
                 : "=r"((r)[0]), "=r"((r)[1]) : "r"(addr))

// ---------------- prep kernels (fp32 -> fp16) ----------------
__global__ void cvt_h_k(const float* __restrict__ in, __half* __restrict__ out, int n8) {
    int i = blockIdx.x * blockDim.x + threadIdx.x;
    if (i < n8) {
        float4 v0 = ((const float4*)in)[i * 2];
        float4 v1 = ((const float4*)in)[i * 2 + 1];
        __half2 h[4];
        h[0] = __floats2half2_rn(v0.x, v0.y);
        h[1] = __floats2half2_rn(v0.z, v0.w);
        h[2] = __floats2half2_rn(v1.x, v1.y);
        h[3] = __floats2half2_rn(v1.z, v1.w);
        ((uint4*)out)[i] = *(uint4*)h;
    }
}

__global__ void transpose_cvt_k(const float* __restrict__ W, __half* __restrict__ Wt) {
    __shared__ float t[32][33];
    int bx = blockIdx.x * 32;   // k (EMBK)
    int by = blockIdx.y * 32;   // n (HID)
    int tx = threadIdx.x, ty = threadIdx.y;
    #pragma unroll
    for (int i = 0; i < 4; i++)
        t[ty + i * 8][tx] = W[(size_t)(bx + ty + i * 8) * HID + (by + tx)];
    __syncthreads();
    #pragma unroll
    for (int i = 0; i < 4; i++)
        Wt[(size_t)(by + ty + i * 8) * EMBK + (bx + tx)] = __float2half(t[tx][ty + i * 8]);
}

// ---------------- fp16 mma.sync GEMM ----------------
// C[m, n0:n0+BN] = act( A[m,:K] @ B[n,:K]^T + bias )
// AMODE 0: A gathered (neigh | traj[sid] | dist), AMODE 1: plain row-major.
// HOUT: store C as half (emb), else float.
template<int AMODE, bool RELU, bool HOUT>
__global__ void __launch_bounds__(NTHR, 2)
gemm_tc(const __half* __restrict__ A,
        const __half* __restrict__ neigh,
        const __half* __restrict__ traj,
        const __half* __restrict__ dist,
        const int*   __restrict__ starts,
        const __half* __restrict__ B,
        const float* __restrict__ bias,
        void* __restrict__ Cv,
        int K, int ldb, int ldc)
{
    extern __shared__ __align__(16) char smem[];
    int* sids = (int*)(smem + NSTAGE * STAGE_BYTES);

    const int tid  = threadIdx.x;
    const int lane = tid & 31;
    const int warp = tid >> 5;
    const int wm = warp >> 2;        // 0..1 : 64-row slab
    const int wn = warp & 3;         // 0..3 : 32-col slab
    const int m0 = blockIdx.x * BM;
    const int n0 = blockIdx.y * BN;

    if (AMODE == 0 && tid < BM) {
        int row = m0 + tid;
        int lo = 0, hi = BSAMP;
        while (lo < hi) {
            int mid = (lo + hi) >> 1;
            if (starts[mid] <= row) lo = mid + 1; else hi = mid;
        }
        sids[tid] = lo - 1;
    }
    if (AMODE == 0) __syncthreads();

    const uint32_t sbase = smem_u32(smem);

    auto load_stage = [&](int s) {
        const uint32_t st = sbase + (uint32_t)((s % NSTAGE) * STAGE_BYTES);
        const int k0 = s * BK;
        // A tile: 128 rows x 32 halves = 64B/row = 4 x 16B chunks; 512 chunks
        #pragma unroll
        for (int i = 0; i < 2; i++) {
            int q = tid + i * NTHR;
            int row = q >> 2, c8 = (q & 3) * 8;          // halves offset
            uint32_t dst = st + (uint32_t)(row * LDSH + c8) * 2u;
            const __half* src;
            int gm = m0 + row;
            int kh = k0 + c8;
            if (AMODE == 1) {
                src = A + (size_t)gm * K + kh;
            } else {
                if (kh < INSZ)
                    src = neigh + (size_t)gm * INSZ + kh;
                else if (kh < INSZ + HID)
                    src = traj + (size_t)sids[row] * HID + (kh - INSZ);
                else
                    src = dist + (size_t)gm * DDIM + (kh - INSZ - HID);
            }
            CP_ASYNC16(dst, src);
        }
        // B tile
        const uint32_t bb = st + (uint32_t)TILE_BYTES;
        #pragma unroll
        for (int i = 0; i < 2; i++) {
            int q = tid + i * NTHR;
            int row = q >> 2, c8 = (q & 3) * 8;
            uint32_t dst = bb + (uint32_t)(row * LDSH + c8) * 2u;
            const __half* src = B + (size_t)(n0 + row) * ldb + (k0 + c8);
            CP_ASYNC16(dst, src);
        }
    };

    float acc[4][4][4];
    #pragma unroll
    for (int mt = 0; mt < 4; mt++)
        #pragma unroll
        for (int nt = 0; nt < 4; nt++)
            #pragma unroll
            for (int j = 0; j < 4; j++) acc[mt][nt][j] = 0.f;

    // per-lane ldmatrix base offsets (bytes, within stage)
    // A: lanes 0-15 -> rows 0..15 col-chunk 0 ; lanes 16-31 -> rows 0..15 col +8 halves
    const uint32_t a_lane = (uint32_t)((wm * 64 + (lane & 15)) * LDSH + (lane >> 4) * 8) * 2u;
    // B (non-trans, [N,K] K-major): lanes 0-7 rows, k-chunk 0; lanes 8-15 same rows k+8
    const uint32_t b_lane = (uint32_t)(TILE_BYTES) +
        (uint32_t)((wn * 32 + (lane & 7)) * LDSH + ((lane >> 3) & 1) * 8) * 2u;

    const int NS = K / BK;
    load_stage(0);
    asm volatile("cp.async.commit_group;\n" ::: "memory");
    load_stage(1);
    asm volatile("cp.async.commit_group;\n" ::: "memory");

    for (int s = 0; s < NS; ++s) {
        if (s + 2 < NS) load_stage(s + 2);
        asm volatile("cp.async.commit_group;\n" ::: "memory");
        asm volatile("cp.async.wait_group 2;\n" ::: "memory");
        __syncthreads();

        const uint32_t st = sbase + (uint32_t)((s % NSTAGE) * STAGE_BYTES);
        #pragma unroll
        for (int kk = 0; kk < 2; kk++) {                  // two k16 steps
            uint32_t a[4][4], b[4][2];
            #pragma unroll
            for (int mt = 0; mt < 4; mt++)
                LDSM_X4(a[mt], st + a_lane + (uint32_t)(mt * 16 * LDSH * 2 + kk * 32));
            #pragma unroll
            for (int nt = 0; nt < 4; nt++)
                LDSM_X2(b[nt], st + b_lane + (uint32_t)(nt * 8 * LDSH * 2 + kk * 32));
            #pragma unroll
            for (int mt = 0; mt < 4; mt++)
                #pragma unroll
                for (int nt = 0; nt < 4; nt++)
                    mma_f16(acc[mt][nt], a[mt], b[nt]);
        }
        __syncthreads();
    }

    // ---------------- epilogue ----------------
    #pragma unroll
    for (int mt = 0; mt < 4; mt++) {
        #pragma unroll
        for (int nt = 0; nt < 4; nt++) {
            int col = n0 + wn * 32 + nt * 8 + 2 * (lane & 3);
            float2 bv = *(const float2*)(bias + col);
            int r0 = m0 + wm * 64 + mt * 16 + (lane >> 2);
            float v0 = acc[mt][nt][0] + bv.x;
            float v1 = acc[mt][nt][1] + bv.y;
            float v2 = acc[mt][nt][2] + bv.x;
            float v3 = acc[mt][nt][3] + bv.y;
            if (RELU) {
                v0 = fmaxf(v0, 0.f); v1 = fmaxf(v1, 0.f);
                v2 = fmaxf(v2, 0.f); v3 = fmaxf(v3, 0.f);
            }
            if (HOUT) {
                __half* C = (__half*)Cv;
                *(__half2*)(C + (size_t)r0 * ldc + col)       = __floats2half2_rn(v0, v1);
                *(__half2*)(C + (size_t)(r0 + 8) * ldc + col) = __floats2half2_rn(v2, v3);
            } else {
                float* C = (float*)Cv;
                *(float2*)(C + (size_t)r0 * ldc + col)       = make_float2(v0, v1);
                *(float2*)(C + (size_t)(r0 + 8) * ldc + col) = make_float2(v2, v3);
            }
        }
    }
}

// ---------------- GRU gates (HBM-bound) ----------------
__device__ __forceinline__ float gru1(float ir, float iz, float inn,
                                      float hr, float hz, float hn, float h)
{
    float r = 1.f / (1.f + expf(-(ir + hr)));
    float z = 1.f / (1.f + expf(-(iz + hz)));
    float nn = tanhf(fmaf(r, hn, inn));
    return fmaf(z, h - nn, nn);
}

__global__ void __launch_bounds__(256)
gates_k(const float* __restrict__ gi, const float* __restrict__ gh,
        const float* __restrict__ ht, float* __restrict__ out)
{
    int idx = blockIdx.x * 256 + threadIdx.x;
    int n  = idx >> 7;
    int h4 = (idx & 127) << 2;
    const float* gir = gi + (size_t)n * G3;
    const float* ghr = gh + (size_t)n * G3;
    float4 ir = *(const float4*)(gir + h4);
    float4 iz = *(const float4*)(gir + HID + h4);
    float4 in_= *(const float4*)(gir + 2 * HID + h4);
    float4 hr = *(const float4*)(ghr + h4);
    float4 hz = *(const float4*)(ghr + HID + h4);
    float4 hn = *(const float4*)(ghr + 2 * HID + h4);
    float4 h  = *(const float4*)(ht + (size_t)n * HID + h4);
    float4 o;
    o.x = gru1(ir.x, iz.x, in_.x, hr.x, hz.x, hn.x, h.x);
    o.y = gru1(ir.y, iz.y, in_.y, hr.y, hz.y, hn.y, h.y);
    o.z = gru1(ir.z, iz.z, in_.z, hr.z, hz.z, hn.z, h.z);
    o.w = gru1(ir.w, iz.w, in_.w, hr.w, hz.w, hn.w, h.w);
    *(float4*)(out + (size_t)n * HID + h4) = o;
}

// ---------------- host ----------------
extern "C" void kernel_launch(void* const* d_in, const int* in_sizes, int n_in,
                              void* d_out, int out_size)
{
    const float* traj  = (const float*)d_in[0];
    const float* neigh = (const float*)d_in[1];
    const float* dist  = (const float*)d_in[2];
    const float* ht    = (const float*)d_in[3];
    const float* W_emb = (const float*)d_in[4];
    const float* b_emb = (const float*)d_in[5];
    const float* w_ih  = (const float*)d_in[6];
    const float* w_hh  = (const float*)d_in[7];
    const float* b_ih  = (const float*)d_in[8];
    const float* b_hh  = (const float*)d_in[9];
    const int*   starts= (const int*)  d_in[10];
    float* out = (float*)d_out;

    float *gi_p, *gh_p;
    __half *emb_p, *wt_p, *wih_p, *whh_p, *nt_p, *ds_p, *tj_p, *htt_p;
    cudaGetSymbolAddress((void**)&gi_p,  g_gi);
    cudaGetSymbolAddress((void**)&gh_p,  g_gh);
    cudaGetSymbolAddress((void**)&emb_p, g_emb);
    cudaGetSymbolAddress((void**)&wt_p,  g_wt);
    cudaGetSymbolAddress((void**)&wih_p, g_wih);
    cudaGetSymbolAddress((void**)&whh_p, g_whh);
    cudaGetSymbolAddress((void**)&nt_p,  g_nt);
    cudaGetSymbolAddress((void**)&ds_p,  g_ds);
    cudaGetSymbolAddress((void**)&tj_p,  g_tj);
    cudaGetSymbolAddress((void**)&htt_p, g_htt);

    cudaFuncSetAttribute(gemm_tc<0, true, true>,
                         cudaFuncAttributeMaxDynamicSharedMemorySize, SMEM_BYTES);
    cudaFuncSetAttribute(gemm_tc<1, false, false>,
                         cudaFuncAttributeMaxDynamicSharedMemorySize, SMEM_BYTES);

    auto cvt = [&](const float* in, __half* o, size_t n) {
        int n8 = (int)(n / 8);
        cvt_h_k<<<(n8 + 255) / 256, 256>>>(in, o, n8);
    };
    cvt(neigh, nt_p,  (size_t)NROWS * INSZ);
    cvt(dist,  ds_p,  (size_t)NROWS * DDIM);
    cvt(traj,  tj_p,  (size_t)BSAMP * HID);
    cvt(ht,    htt_p, (size_t)NROWS * HID);
    cvt(w_ih,  wih_p, (size_t)G3 * HID);
    cvt(w_hh,  whh_p, (size_t)G3 * HID);
    transpose_cvt_k<<<dim3(EMBK / 32, HID / 32), dim3(32, 8)>>>(W_emb, wt_p);

    // emb = relu(X @ W_emb + b), X gathered; output half (A of GEMM2)
    gemm_tc<0, true, true><<<dim3(NROWS / BM, HID / BN), NTHR, SMEM_BYTES>>>(
        nullptr, nt_p, tj_p, ds_p, starts, wt_p, b_emb, emb_p, EMBK, EMBK, HID);

    // gi = emb @ w_ih^T + b_ih
    gemm_tc<1, false, false><<<dim3(NROWS / BM, G3 / BN), NTHR, SMEM_BYTES>>>(
        emb_p, nullptr, nullptr, nullptr, nullptr, wih_p, b_ih, gi_p, HID, HID, G3);

    // gh = ht @ w_hh^T + b_hh
    gemm_tc<1, false, false><<<dim3(NROWS / BM, G3 / BN), NTHR, SMEM_BYTES>>>(
        htt_p, nullptr, nullptr, nullptr, nullptr, whh_p, b_hh, gh_p, HID, HID, G3);

    gates_k<<<(NROWS * HID / 4) / 256, 256>>>(gi_p, gh_p, ht, out);
}